// round 14
// baseline (speedup 1.0000x reference)
#include <cuda_runtime.h>
#include <cuda_bf16.h>
#include <cuda_fp16.h>
#include <cstdint>

// Y(8192x2048) = X(8192x2048) @ W(2048x2048), W = TR(f0,f1,f2,f3), rank-64 per i2-parity.
//   B[r][l*64+ab] = sum_k f0[a,i1,k] f1[k,i2,b],  i1=r>>5, i2=2(r&31)+l, ab=a*8+b
//   C[ab][i3*16+i4] = sum_k f2[b,i3,k] f3[k,i4,a]
//   Z = X @ B (8192x128);  Y[:, l*1024+c'] = Z[:, l*64:+64] @ C
// Single fused kernel per 32-row slab: phase 1 computes Z-slab (tcgen-style
// pipelined fp16 HMMA), Z kept in smem; phase 2 streams C and writes Y.
// Single-pass fp16 both phases (total err ~4.5e-4, validated R12/R13).

__device__ __half g_Bf16[2048 * 128];
__device__ __half g_Cf16[64 * 1024];

static __device__ __forceinline__ uint32_t sptr(const void* p) {
    return (uint32_t)__cvta_generic_to_shared(p);
}
static __device__ __forceinline__ void ldm_a(uint32_t addr, uint32_t* r) {
    asm volatile("ldmatrix.sync.aligned.m8n8.x4.shared.b16 {%0,%1,%2,%3}, [%4];"
                 : "=r"(r[0]), "=r"(r[1]), "=r"(r[2]), "=r"(r[3]) : "r"(addr));
}
static __device__ __forceinline__ void ldm_bt(uint32_t addr, uint32_t* r) {
    asm volatile("ldmatrix.sync.aligned.m8n8.x4.trans.shared.b16 {%0,%1,%2,%3}, [%4];"
                 : "=r"(r[0]), "=r"(r[1]), "=r"(r[2]), "=r"(r[3]) : "r"(addr));
}
static __device__ __forceinline__ void mma_f16(float* c, const uint32_t* a,
                                               uint32_t b0, uint32_t b1) {
    asm volatile("mma.sync.aligned.m16n8k16.row.col.f32.f16.f16.f32 "
                 "{%0,%1,%2,%3}, {%4,%5,%6,%7}, {%8,%9}, {%0,%1,%2,%3};"
                 : "+f"(c[0]), "+f"(c[1]), "+f"(c[2]), "+f"(c[3])
                 : "r"(a[0]), "r"(a[1]), "r"(a[2]), "r"(a[3]), "r"(b0), "r"(b1));
}
#define CP16(dst, src)                                                        \
    asm volatile("cp.async.cg.shared.global [%0], [%1], 16;" ::"r"(dst), "l"(src))
#define CP_COMMIT() asm volatile("cp.async.commit_group;")
#define CP_WAIT0() asm volatile("cp.async.wait_group 0;")

static __device__ __forceinline__ uint32_t h2u(__half2 h) {
    return *reinterpret_cast<uint32_t*>(&h);
}

// ---------------------------------------------------------------------------
// K1: build B (fp16) and C (fp16) from TR factors.
// ---------------------------------------------------------------------------
__global__ void build_BC(const float* __restrict__ f0, const float* __restrict__ f1,
                         const float* __restrict__ f2, const float* __restrict__ f3) {
    int idx = blockIdx.x * blockDim.x + threadIdx.x;
    const int NB = 2048 * 128;
    if (idx < NB) {
        int r = idx >> 7, j = idx & 127;
        int l = j >> 6, ab = j & 63, a = ab >> 3, b = ab & 7;
        int i1 = r >> 5, i2 = ((r & 31) << 1) | l;
        float s = 0.0f;
#pragma unroll
        for (int k = 0; k < 8; k++)
            s = fmaf(f0[a * 512 + i1 * 8 + k], f1[k * 512 + i2 * 8 + b], s);
        g_Bf16[idx] = __float2half_rn(s);
    } else {
        int t = idx - NB;
        if (t < 64 * 1024) {
            int ab = t >> 10, c = t & 1023;
            int a = ab >> 3, b = ab & 7, i3 = c >> 4, i4 = c & 15;
            float s = 0.0f;
#pragma unroll
            for (int k = 0; k < 8; k++)
                s = fmaf(f2[b * 512 + i3 * 8 + k], f3[k * 128 + i4 * 8 + a], s);
            g_Cf16[t] = __float2half_rn(s);
        }
    }
}

// ---------------------------------------------------------------------------
// K2 (fused): per 32-row slab (grid 256):
//   Phase 1: Zslab(32x128) = X[m0:m0+32,:] @ B     (BK=64, double-buffered)
//   Phase 2: Y[m0:m0+32, :] = Zslab(l half) @ C    (16 n-chunks of 128,
//            C chunks double-buffered in the phase-1 stage area)
// SMEM map (bytes):
//   [0, 52224)   phase-1 stages (2 x 26112: X fp32 32x68, B fp16 64x136)
//                phase-2 reuses [s*17408, +17408) for C chunks (64x136 fp16)
//   [52224, 60928) Zs fp16 32x136
// ---------------------------------------------------------------------------
__global__ __launch_bounds__(256) void fused(const float* __restrict__ X,
                                             float* __restrict__ Y) {
    const int STAGE_B = 26112;
    const int XB = 8704;          // X region bytes within stage
    const int LDX = 68;           // fp32 per X row (272 B)
    const int ZS_OFF = 52224;     // Zs offset (32 x 136 fp16)
    extern __shared__ __align__(16) char sm[];
    const uint32_t smb = sptr(sm);
    const uint32_t zsm = smb + ZS_OFF;

    const int tid = threadIdx.x, lane = tid & 31, wid = tid >> 5;
    const int m0 = blockIdx.x * 32;
    const int wm = (wid & 1) * 16, wn = (wid >> 1) * 32;
    const int gid = lane >> 2, tig2 = (lane & 3) * 2;

    // ======================= Phase 1: Z slab =======================
    float acc[4][4];
#pragma unroll
    for (int nt = 0; nt < 4; nt++)
#pragma unroll
        for (int e = 0; e < 4; e++) acc[nt][e] = 0.0f;

    auto load_tile = [&](int it, int s) {
        const int k0 = it * 64;
        const uint32_t base = smb + s * STAGE_B;
#pragma unroll
        for (int i = 0; i < 2; i++) {
            int p = tid + i * 256;
            int row = p >> 4, c4 = (p & 15) * 4;
            CP16(base + row * 272 + c4 * 4, &X[(m0 + row) * 2048 + k0 + c4]);
        }
#pragma unroll
        for (int i = 0; i < 4; i++) {
            int p = tid + i * 256;
            int row = p >> 4, c8 = (p & 15) * 8;
            CP16(base + XB + row * 272 + c8 * 2, &g_Bf16[(k0 + row) * 128 + c8]);
        }
        CP_COMMIT();
    };

    load_tile(0, 0);

    for (int it = 0; it < 32; ++it) {
        CP_WAIT0();
        __syncthreads();
        const int cur = it & 1;
        if (it + 1 < 32) load_tile(it + 1, (it + 1) & 1);

        const float* xs = (const float*)(sm + cur * STAGE_B);
        const uint32_t bsm = smb + cur * STAGE_B + XB;
        const int r0 = (wm + gid) * LDX, r1 = r0 + 8 * LDX;

#pragma unroll
        for (int kk = 0; kk < 64; kk += 16) {
            float2 v00 = *(const float2*)&xs[r0 + kk + tig2];
            float2 v10 = *(const float2*)&xs[r1 + kk + tig2];
            float2 v01 = *(const float2*)&xs[r0 + kk + 8 + tig2];
            float2 v11 = *(const float2*)&xs[r1 + kk + 8 + tig2];
            uint32_t a[4];
            a[0] = h2u(__floats2half2_rn(v00.x, v00.y));
            a[1] = h2u(__floats2half2_rn(v10.x, v10.y));
            a[2] = h2u(__floats2half2_rn(v01.x, v01.y));
            a[3] = h2u(__floats2half2_rn(v11.x, v11.y));
            uint32_t bh[2][4];
            int brow = kk + (lane & 7) + ((lane >> 3) & 1) * 8;
#pragma unroll
            for (int h = 0; h < 2; h++) {
                int bcol = wn + h * 16 + (lane >> 4) * 8;
                ldm_bt(bsm + brow * 272 + bcol * 2, bh[h]);
            }
#pragma unroll
            for (int nt = 0; nt < 4; nt++) {
                int h = nt >> 1, q = (nt & 1) * 2;
                mma_f16(acc[nt], a, bh[h][q], bh[h][q + 1]);
            }
        }
    }

    // All phase-1 compute done; stage buffers free for C chunks.
    __syncthreads();

    // ======================= Phase 2: Y = Z @ C =======================
    auto load_C = [&](int ch, int s) {
        const int c0 = (ch & 7) * 128;
        const uint32_t base = smb + s * 17408;
#pragma unroll
        for (int i = 0; i < 4; i++) {
            int p = tid + i * 256;
            int row = p >> 4, c8 = (p & 15) * 8;
            CP16(base + row * 272 + c8 * 2, &g_Cf16[row * 1024 + c0 + c8]);
        }
        CP_COMMIT();
    };

    load_C(0, 0);

    // Epilogue of phase 1: Z slab -> smem fp16 (LDZ=136), overlaps C load 0.
#pragma unroll
    for (int nt = 0; nt < 4; nt++) {
        int rowl = wm + (lane >> 2);
        int col = wn + nt * 8 + (lane & 3) * 2;
        const float* c = acc[nt];
#pragma unroll
        for (int half = 0; half < 2; half++) {
            __half2 z2 = __floats2half2_rn(c[half * 2 + 0], c[half * 2 + 1]);
            *(__half2*)(sm + ZS_OFF + ((rowl + half * 8) * 136 + col) * 2) = z2;
        }
    }

    for (int ch = 0; ch < 16; ++ch) {
        CP_WAIT0();
        __syncthreads();   // C chunk ready + Zs visible (ch=0) + prev chunk consumed
        if (ch + 1 < 16) load_C(ch + 1, (ch + 1) & 1);

        const int l = ch >> 3;
        const int n0 = ch * 128;
        const uint32_t csm = smb + (ch & 1) * 17408;

        float ac2[4][4];
#pragma unroll
        for (int nt = 0; nt < 4; nt++)
#pragma unroll
            for (int e = 0; e < 4; e++) ac2[nt][e] = 0.0f;

#pragma unroll
        for (int kk = 0; kk < 64; kk += 16) {
            uint32_t a[4];
            {
                int arow = wm + (lane & 15);
                int acol = l * 64 + kk + ((lane >> 4) << 3);
                ldm_a(zsm + (arow * 136 + acol) * 2, a);
            }
            uint32_t bh[2][4];
            int brow = kk + (lane & 7) + ((lane >> 3) & 1) * 8;
#pragma unroll
            for (int h = 0; h < 2; h++) {
                int bcol = wn + h * 16 + (lane >> 4) * 8;
                ldm_bt(csm + brow * 272 + bcol * 2, bh[h]);
            }
#pragma unroll
            for (int nt = 0; nt < 4; nt++) {
                int h = nt >> 1, q = (nt & 1) * 2;
                mma_f16(ac2[nt], a, bh[h][q], bh[h][q + 1]);
            }
        }

#pragma unroll
        for (int nt = 0; nt < 4; nt++) {
            int row = m0 + wm + (lane >> 2);
            int col = n0 + wn + nt * 8 + (lane & 3) * 2;
            const float* c = ac2[nt];
            *(float2*)&Y[row * 2048 + col] = make_float2(c[0], c[1]);
            *(float2*)&Y[(row + 8) * 2048 + col] = make_float2(c[2], c[3]);
        }
    }
}

// ---------------------------------------------------------------------------
extern "C" void kernel_launch(void* const* d_in, const int* in_sizes, int n_in,
                              void* d_out, int out_size) {
    cudaFuncSetAttribute(fused, cudaFuncAttributeMaxDynamicSharedMemorySize, 60928);

    const float* x = (const float*)d_in[0];
    const float* f0 = (const float*)d_in[1];
    const float* f1 = (const float*)d_in[2];
    const float* f2 = (const float*)d_in[3];
    const float* f3 = (const float*)d_in[4];
    float* y = (float*)d_out;

    build_BC<<<1280, 256>>>(f0, f1, f2, f3);
    fused<<<256, 256, 60928>>>(x, y);
}